// round 6
// baseline (speedup 1.0000x reference)
#include <cuda_runtime.h>
#include <cstdint>

#define NL   28
#define DIM  1024
#define NH   16
#define HD   64
#define FFN  2816
#define VOCAB 32000

#define KS_QKV 8     // qkv ksplit   (K=1024 -> 128 rows/block)
#define KS_O   16    // attn ksplit  (K=1024 -> 64 rows/block)
#define KS_GU  8     // gate/up ksplit (K=1024 -> 128 rows/block)
#define KS_D   11    // down ksplit  (K=2816 -> 256 rows/block)

// ---------------- device scratch ----------------
__device__ float g_h[2][DIM];       // residual incl. prev-layer MLP (written by k_qkv)
__device__ float g_h1[2][DIM];      // residual incl. attn (written by k_gateup; init=emb)
__device__ float g_hn[2][DIM];      // final normed hidden
__device__ float g_qkv_part[KS_QKV][2][3 * DIM];
__device__ float g_o_part[KS_O][2][DIM];
__device__ float g_gate_part[KS_GU][2][FFN];
__device__ float g_up_part[KS_GU][2][FFN];
__device__ float g_d_part[KS_D][2][DIM];

// ---------------- helpers ----------------
__device__ __forceinline__ float block_sum(float v) {
    __shared__ float sh[8];
    int lane = threadIdx.x & 31, w = threadIdx.x >> 5;
#pragma unroll
    for (int o = 16; o; o >>= 1) v += __shfl_xor_sync(0xffffffffu, v, o);
    __syncthreads();
    if (lane == 0) sh[w] = v;
    __syncthreads();
    float r = sh[0];
#pragma unroll
    for (int i = 1; i < 8; i++) r += sh[i];
    return r;
}

#define FMA8(w4, x0, x1)                                                   \
    a[0] += (x0) * (w4).x; a[1] += (x0) * (w4).y;                          \
    a[2] += (x0) * (w4).z; a[3] += (x0) * (w4).w;                          \
    a[4] += (x1) * (w4).x; a[5] += (x1) * (w4).y;                          \
    a[6] += (x1) * (w4).z; a[7] += (x1) * (w4).w;

// ---------------- init: g_h1 <- emb, zero d_part ----------------
__global__ void k_init(const float* __restrict__ emb) {
    int i = blockIdx.x * blockDim.x + threadIdx.x;
    if (i < 2 * DIM) g_h1[i / DIM][i % DIM] = emb[i];
    if (i < KS_D * 2 * DIM) ((float*)g_d_part)[i] = 0.f;
}

// ---------------- K1: residual merge + rms1 + QKV GEMV -------------------
// grid 192 = 24 col-groups(128) x 8 ksplit, block 256
__global__ void __launch_bounds__(256) k_qkv(const float* __restrict__ wq,
                                             const float* __restrict__ wk,
                                             const float* __restrict__ wv,
                                             const float* __restrict__ ln1) {
    __shared__ float xs[2][DIM];
    __shared__ float red[8][32][8];
    int t = threadIdx.x, lane = t & 31, wid = t >> 5;
    int cg = blockIdx.x % 24, ks = blockIdx.x / 24;

    float s0 = 0.f, s1 = 0.f;
    for (int i = t; i < DIM; i += 256) {
        float v0 = g_h1[0][i], v1 = g_h1[1][i];
#pragma unroll
        for (int k = 0; k < KS_D; k++) {
            v0 += g_d_part[k][0][i];
            v1 += g_d_part[k][1][i];
        }
        g_h[0][i] = v0; g_h[1][i] = v1;
        xs[0][i] = v0;  xs[1][i] = v1;
        s0 += v0 * v0;  s1 += v1 * v1;
    }
    s0 = block_sum(s0);
    s1 = block_sum(s1);
    float r0 = rsqrtf(s0 * (1.f / DIM) + 1e-5f);
    float r1 = rsqrtf(s1 * (1.f / DIM) + 1e-5f);
    for (int i = t; i < DIM; i += 256) {
        float g = ln1[i];
        xs[0][i] *= r0 * g;
        xs[1][i] *= r1 * g;
    }
    __syncthreads();

    int e0 = cg * 128;
    const float* W; int ecol;
    if (e0 < DIM)          { W = wq; ecol = e0; }
    else if (e0 < 2 * DIM) { W = wk; ecol = e0 - DIM; }
    else                   { W = wv; ecol = e0 - 2 * DIM; }

    int d0 = ks * 128 + wid;
    const float* base = W + ecol + lane * 4;
    float a[8] = {0,0,0,0,0,0,0,0};
#pragma unroll
    for (int gg = 0; gg < 2; gg++) {
        float4 w[8];
#pragma unroll
        for (int r = 0; r < 8; r++)
            w[r] = *(const float4*)(base + (size_t)(d0 + (gg * 8 + r) * 8) * DIM);
#pragma unroll
        for (int r = 0; r < 8; r++) {
            int d = d0 + (gg * 8 + r) * 8;
            float x0 = xs[0][d], x1 = xs[1][d];
            FMA8(w[r], x0, x1);
        }
    }
#pragma unroll
    for (int j = 0; j < 8; j++) red[wid][lane][j] = a[j];
    __syncthreads();
    {
        int lane2 = t >> 3, j = t & 7;
        float s = 0.f;
#pragma unroll
        for (int w = 0; w < 8; w++) s += red[w][lane2][j];
        g_qkv_part[ks][j >> 2][e0 + lane2 * 4 + (j & 3)] = s;
    }
}

// ---------------- K2: qkv-merge + RoPE + attn + O GEMV -------------------
// grid 128 = 8 col-groups(128) x 16 ksplit, block 256
__global__ void __launch_bounds__(256) k_attn_o(const float* __restrict__ wo,
                                                const int* __restrict__ cpos) {
    __shared__ float qs[2][3 * DIM];
    __shared__ float xo[2][DIM];
    __shared__ float red[8][32][8];
    int t = threadIdx.x, lane = t & 31, wid = t >> 5;
    int cg = blockIdx.x & 7, ks = blockIdx.x >> 3;

    for (int i = t; i < 3 * DIM; i += 256) {
        float s0 = 0.f, s1 = 0.f;
#pragma unroll
        for (int k = 0; k < KS_QKV; k++) {
            s0 += g_qkv_part[k][0][i];
            s1 += g_qkv_part[k][1][i];
        }
        qs[0][i] = s0; qs[1][i] = s1;
    }
    __syncthreads();

    int pos = cpos[0];
    float inv_freq = __expf(-(float)(2 * lane) * (1.f / HD) * logf(10000.f));
    float ang = (float)pos * inv_freq;
    float cs = cosf(ang), sn = sinf(ang);

#pragma unroll
    for (int pp = 0; pp < 4; pp++) {
        int pair = wid * 4 + pp;          // 32 pairs = 2 tokens x 16 heads
        int b = pair >> 4, h = pair & 15;
        const float* q = &qs[b][h * HD];
        const float* k = &qs[b][DIM + h * HD];
        const float* v = &qs[b][2 * DIM + h * HD];
        float q1 = q[lane], q2 = q[lane + 32];
        float k1 = k[lane], k2 = k[lane + 32];
        float q1r = q1 * cs - q2 * sn, q2r = q2 * cs + q1 * sn;
        float k1r = k1 * cs - k2 * sn, k2r = k2 * cs + k1 * sn;
        float dot = q1r * k1r + q2r * k2r;
#pragma unroll
        for (int o = 16; o; o >>= 1) dot += __shfl_xor_sync(0xffffffffu, dot, o);
        float s = dot * 0.125f;
        float m = fmaxf(s, 0.f);
        float es = __expf(s - m);
        float w = es / (es + 2047.f * __expf(-m));
        xo[b][h * HD + lane]      = w * v[lane];
        xo[b][h * HD + lane + 32] = w * v[lane + 32];
    }
    __syncthreads();

    int e0 = cg * 128;
    int d0 = ks * 64 + wid;
    const float* base = wo + e0 + lane * 4;
    float a[8] = {0,0,0,0,0,0,0,0};
    {
        float4 w[8];
#pragma unroll
        for (int r = 0; r < 8; r++)
            w[r] = *(const float4*)(base + (size_t)(d0 + r * 8) * DIM);
#pragma unroll
        for (int r = 0; r < 8; r++) {
            int d = d0 + r * 8;
            float x0 = xo[0][d], x1 = xo[1][d];
            FMA8(w[r], x0, x1);
        }
    }
#pragma unroll
    for (int j = 0; j < 8; j++) red[wid][lane][j] = a[j];
    __syncthreads();
    {
        int lane2 = t >> 3, j = t & 7;
        float s = 0.f;
#pragma unroll
        for (int w = 0; w < 8; w++) s += red[w][lane2][j];
        g_o_part[ks][j >> 2][e0 + lane2 * 4 + (j & 3)] = s;
    }
}

// ---------------- K3: residual merge + rms2 + gate|up GEMV ---------------
// grid 352 = 2 halves x (22 col-groups(128) x 8 ksplit), block 256
__global__ void __launch_bounds__(256) k_gateup(const float* __restrict__ wg,
                                                const float* __restrict__ wu,
                                                const float* __restrict__ ln2) {
    __shared__ float xs[2][DIM];
    __shared__ float red[8][32][8];
    int t = threadIdx.x, lane = t & 31, wid = t >> 5;
    int half = blockIdx.x / 176;
    int bb = blockIdx.x % 176;
    int cg = bb % 22, ks = bb / 22;

    float s0 = 0.f, s1 = 0.f;
    for (int i = t; i < DIM; i += 256) {
        float v0 = g_h[0][i], v1 = g_h[1][i];
#pragma unroll
        for (int k = 0; k < KS_O; k++) {
            v0 += g_o_part[k][0][i];
            v1 += g_o_part[k][1][i];
        }
        g_h1[0][i] = v0; g_h1[1][i] = v1;
        xs[0][i] = v0;   xs[1][i] = v1;
        s0 += v0 * v0;   s1 += v1 * v1;
    }
    s0 = block_sum(s0);
    s1 = block_sum(s1);
    float r0 = rsqrtf(s0 * (1.f / DIM) + 1e-5f);
    float r1 = rsqrtf(s1 * (1.f / DIM) + 1e-5f);
    for (int i = t; i < DIM; i += 256) {
        float g = ln2[i];
        xs[0][i] *= r0 * g;
        xs[1][i] *= r1 * g;
    }
    __syncthreads();

    int e0 = cg * 128;
    const float* W = half ? wu : wg;
    float* dst = half ? (float*)g_up_part : (float*)g_gate_part;

    int d0 = ks * 128 + wid;
    const float* base = W + e0 + lane * 4;
    float a[8] = {0,0,0,0,0,0,0,0};
#pragma unroll
    for (int gg = 0; gg < 2; gg++) {
        float4 w[8];
#pragma unroll
        for (int r = 0; r < 8; r++)
            w[r] = *(const float4*)(base + (size_t)(d0 + (gg * 8 + r) * 8) * FFN);
#pragma unroll
        for (int r = 0; r < 8; r++) {
            int d = d0 + (gg * 8 + r) * 8;
            float x0 = xs[0][d], x1 = xs[1][d];
            FMA8(w[r], x0, x1);
        }
    }
#pragma unroll
    for (int j = 0; j < 8; j++) red[wid][lane][j] = a[j];
    __syncthreads();
    {
        int lane2 = t >> 3, j = t & 7;
        float s = 0.f;
#pragma unroll
        for (int w = 0; w < 8; w++) s += red[w][lane2][j];
        dst[(size_t)ks * 2 * FFN + (size_t)(j >> 2) * FFN + e0 + lane2 * 4 + (j & 3)] = s;
    }
}

// ---------------- K4: silu-merge + down GEMV -----------------------------
// grid 88 = 8 col-groups(128) x 11 ksplit, block 256
__global__ void __launch_bounds__(256) k_down(const float* __restrict__ wd) {
    __shared__ float xs[2][FFN];
    __shared__ float red[8][32][8];
    int t = threadIdx.x, lane = t & 31, wid = t >> 5;
    int cg = blockIdx.x & 7, ks = blockIdx.x >> 3;

    for (int i = t; i < FFN; i += 256) {
        float g0 = 0.f, g1 = 0.f, u0 = 0.f, u1 = 0.f;
#pragma unroll
        for (int k = 0; k < KS_GU; k++) {
            g0 += g_gate_part[k][0][i];
            g1 += g_gate_part[k][1][i];
            u0 += g_up_part[k][0][i];
            u1 += g_up_part[k][1][i];
        }
        xs[0][i] = g0 / (1.f + __expf(-g0)) * u0;
        xs[1][i] = g1 / (1.f + __expf(-g1)) * u1;
    }
    __syncthreads();

    int e0 = cg * 128;
    int d0 = ks * 256 + wid;
    const float* base = wd + e0 + lane * 4;
    float a[8] = {0,0,0,0,0,0,0,0};
#pragma unroll
    for (int gg = 0; gg < 4; gg++) {
        float4 w[8];
#pragma unroll
        for (int r = 0; r < 8; r++)
            w[r] = *(const float4*)(base + (size_t)(d0 + (gg * 8 + r) * 8) * DIM);
#pragma unroll
        for (int r = 0; r < 8; r++) {
            int d = d0 + (gg * 8 + r) * 8;
            float x0 = xs[0][d], x1 = xs[1][d];
            FMA8(w[r], x0, x1);
        }
    }
#pragma unroll
    for (int j = 0; j < 8; j++) red[wid][lane][j] = a[j];
    __syncthreads();
    {
        int lane2 = t >> 3, j = t & 7;
        float s = 0.f;
#pragma unroll
        for (int w = 0; w < 8; w++) s += red[w][lane2][j];
        g_d_part[ks][j >> 2][e0 + lane2 * 4 + (j & 3)] = s;
    }
}

// ---------------- K5: final residual merge + rms -------------------------
__global__ void __launch_bounds__(256) k_final(const float* __restrict__ normw,
                                               float* __restrict__ out) {
    __shared__ float xs[2][DIM];
    int t = threadIdx.x;
    float s0 = 0.f, s1 = 0.f;
    for (int i = t; i < DIM; i += 256) {
        float v0 = g_h1[0][i], v1 = g_h1[1][i];
#pragma unroll
        for (int k = 0; k < KS_D; k++) {
            v0 += g_d_part[k][0][i];
            v1 += g_d_part[k][1][i];
        }
        xs[0][i] = v0; xs[1][i] = v1;
        s0 += v0 * v0; s1 += v1 * v1;
    }
    s0 = block_sum(s0);
    s1 = block_sum(s1);
    float r0 = rsqrtf(s0 * (1.f / DIM) + 1e-5f);
    float r1 = rsqrtf(s1 * (1.f / DIM) + 1e-5f);
    for (int i = t; i < DIM; i += 256) {
        float g = normw[i];
        float h0 = xs[0][i] * r0 * g;
        float h1 = xs[1][i] * r1 * g;
        g_hn[0][i] = h0;
        g_hn[1][i] = h1;
        out[i]       = h0;
        out[DIM + i] = h1;
    }
}

// ---------------- K6: lm_head GEMV. grid 250 col-groups(128) --------------
__global__ void __launch_bounds__(256) k_lmhead(const float* __restrict__ wlm,
                                                float* __restrict__ out) {
    __shared__ float xs[2][DIM];
    __shared__ float red[8][32][8];
    int t = threadIdx.x, lane = t & 31, wid = t >> 5;
    for (int i = t; i < DIM; i += 256) {
        xs[0][i] = g_hn[0][i];
        xs[1][i] = g_hn[1][i];
    }
    __syncthreads();

    int e0 = blockIdx.x * 128;
    const float* base = wlm + e0 + lane * 4;
    float a[8] = {0,0,0,0,0,0,0,0};
#pragma unroll
    for (int gg = 0; gg < 16; gg++) {
        float4 w[8];
#pragma unroll
        for (int r = 0; r < 8; r++)
            w[r] = *(const float4*)(base + (size_t)(wid + (gg * 8 + r) * 8) * VOCAB);
#pragma unroll
        for (int r = 0; r < 8; r++) {
            int d = wid + (gg * 8 + r) * 8;
            float x0 = xs[0][d], x1 = xs[1][d];
            FMA8(w[r], x0, x1);
        }
    }
#pragma unroll
    for (int j = 0; j < 8; j++) red[wid][lane][j] = a[j];
    __syncthreads();
    {
        int lane2 = t >> 3, j = t & 7;
        float s = 0.f;
#pragma unroll
        for (int w = 0; w < 8; w++) s += red[w][lane2][j];
        out[2 * DIM + (size_t)(j >> 2) * VOCAB + e0 + lane2 * 4 + (j & 3)] = s;
    }
}

// ---------------- launcher ----------------
extern "C" void kernel_launch(void* const* d_in, const int* in_sizes, int n_in,
                              void* d_out, int out_size) {
    const float* emb  = (const float*)d_in[0];
    const int*   cpos = (const int*)d_in[2];
    const float* wq   = (const float*)d_in[4];
    const float* wk   = (const float*)d_in[5];
    const float* wv   = (const float*)d_in[6];
    const float* wo   = (const float*)d_in[7];
    const float* wg   = (const float*)d_in[8];
    const float* wu   = (const float*)d_in[9];
    const float* wd   = (const float*)d_in[10];
    const float* ln1  = (const float*)d_in[11];
    const float* ln2  = (const float*)d_in[12];
    const float* nw   = (const float*)d_in[13];
    const float* wlm  = (const float*)d_in[14];
    float* out = (float*)d_out;

    k_init<<<22, 1024>>>(emb);
    for (int l = 0; l < NL; l++) {
        size_t oqk = (size_t)l * DIM * DIM;
        size_t ogu = (size_t)l * DIM * FFN;
        k_qkv   <<<192, 256>>>(wq + oqk, wk + oqk, wv + oqk, ln1 + l * DIM);
        k_attn_o<<<128, 256>>>(wo + oqk, cpos);
        k_gateup<<<352, 256>>>(wg + ogu, wu + ogu, ln2 + l * DIM);
        k_down  <<<88,  256>>>(wd + ogu);
    }
    k_final <<<1,   256>>>(nw, out);
    k_lmhead<<<250, 256>>>(wlm, out);
}

// round 7
// speedup vs baseline: 2.0159x; 2.0159x over previous
#include <cuda_runtime.h>
#include <cstdint>

#define NL   28
#define DIM  1024
#define NH   16
#define HD   64
#define FFN  2816
#define VOCAB 32000

// ---------------- device scratch ----------------
__device__ float g_h[2][DIM];              // residual stream (atomically updated)
__device__ float g_qkv[2][2][3 * DIM];     // [parity][batch][q|k|v]
__device__ float g_gp[2][2][2][FFN];       // [parity][gate/up][batch][col]
__device__ float g_hn[2][DIM];             // final normed hidden

// ---------------- helpers ----------------
__device__ __forceinline__ float block_sum(float v) {
    __shared__ float sh[8];
    int lane = threadIdx.x & 31, w = threadIdx.x >> 5;
#pragma unroll
    for (int o = 16; o; o >>= 1) v += __shfl_xor_sync(0xffffffffu, v, o);
    __syncthreads();
    if (lane == 0) sh[w] = v;
    __syncthreads();
    float r = sh[0];
#pragma unroll
    for (int i = 1; i < 8; i++) r += sh[i];
    return r;
}

#define FMA8(w4, x0, x1)                                                   \
    a[0] += (x0) * (w4).x; a[1] += (x0) * (w4).y;                          \
    a[2] += (x0) * (w4).z; a[3] += (x0) * (w4).w;                          \
    a[4] += (x1) * (w4).x; a[5] += (x1) * (w4).y;                          \
    a[6] += (x1) * (w4).z; a[7] += (x1) * (w4).w;

// 64-col tile GEMV: thread (rr = t>>4, c4 = t&15); pthr pre-offset to
// row (RB0+rr), col (e0 + 4*c4). xs pre-offset so local index = rr + p*16.
template<int LD, int NPASS>
__device__ __forceinline__ void gemv64(const float* __restrict__ pthr,
                                       const float* __restrict__ xs0,
                                       const float* __restrict__ xs1,
                                       int rr, float* a) {
    constexpr int G = NPASS < 8 ? NPASS : 8;
#pragma unroll
    for (int g = 0; g < NPASS; g += G) {
        float4 w[G];
#pragma unroll
        for (int r = 0; r < G; r++)
            w[r] = *(const float4*)(pthr + (size_t)(g + r) * 16 * LD);
#pragma unroll
        for (int r = 0; r < G; r++) {
            int d = rr + (g + r) * 16;
            float x0 = xs0[d], x1 = xs1[d];
            FMA8(w[r], x0, x1);
        }
    }
}

// reduce a[8] over the 16 row-threads per col-quad. Returns true for t<128
// with s = sum, b = batch, col = column offset within the 64-col tile.
__device__ __forceinline__ bool tile_reduce(float* a, float& s, int& b, int& col) {
    __shared__ float red[8][16][8];
    int t = threadIdx.x, lane = t & 31, wid = t >> 5;
#pragma unroll
    for (int j = 0; j < 8; j++) a[j] += __shfl_xor_sync(0xffffffffu, a[j], 16);
    if (lane < 16)
#pragma unroll
        for (int j = 0; j < 8; j++) red[wid][lane][j] = a[j];
    __syncthreads();
    if (t >= 128) return false;
    int c4 = t >> 3, j = t & 7;
    float acc = 0.f;
#pragma unroll
    for (int w = 0; w < 8; w++) acc += red[w][c4][j];
    s = acc; b = j >> 2; col = c4 * 4 + (j & 3);
    return true;
}

// rms prologue: xs[b][i] = rms(g_h[b]) * gamma[i]
__device__ __forceinline__ void rms_x(const float* __restrict__ gamma,
                                      float (*xs)[DIM]) {
    int t = threadIdx.x;
    float s0 = 0.f, s1 = 0.f;
    for (int i = t; i < DIM; i += 256) {
        float v0 = g_h[0][i], v1 = g_h[1][i];
        xs[0][i] = v0; xs[1][i] = v1;
        s0 += v0 * v0; s1 += v1 * v1;
    }
    s0 = block_sum(s0);
    s1 = block_sum(s1);
    float r0 = rsqrtf(s0 * (1.f / DIM) + 1e-5f);
    float r1 = rsqrtf(s1 * (1.f / DIM) + 1e-5f);
    for (int i = t; i < DIM; i += 256) {
        float g = gamma[i];
        xs[0][i] *= r0 * g;
        xs[1][i] *= r1 * g;
    }
    __syncthreads();
}

// ---------------- init: residual <- emb, zero parity-0 accumulators ------
__global__ void k_init(const float* __restrict__ emb) {
    int i = blockIdx.x * blockDim.x + threadIdx.x;
    if (i < 2 * DIM) g_h[i / DIM][i % DIM] = emb[i];
    int z = i - 2 * DIM;
    if (z >= 0) {
        if (z < 2 * 3 * DIM)            ((float*)g_qkv[0])[z] = 0.f;
        else if (z < 2*3*DIM + 4*FFN)   ((float*)g_gp[0])[z - 2*3*DIM] = 0.f;
    }
}

// ---------------- K1: rms1 + QKV GEMV. grid 384 = 48cg x 8ks -------------
__global__ void __launch_bounds__(256) k_qkv(const float* __restrict__ wq,
                                             const float* __restrict__ wk,
                                             const float* __restrict__ wv,
                                             const float* __restrict__ ln1,
                                             int par) {
    __shared__ float xs[2][DIM];
    rms_x(ln1, xs);

    int t = threadIdx.x, rr = t >> 4, c4 = t & 15;
    int cg = blockIdx.x % 48, ks = blockIdx.x / 48;
    int e0 = cg * 64, RB0 = ks * 128;
    const float* W; int ec;
    if (e0 < DIM)          { W = wq; ec = e0; }
    else if (e0 < 2 * DIM) { W = wk; ec = e0 - DIM; }
    else                   { W = wv; ec = e0 - 2 * DIM; }

    const float* pthr = W + (size_t)(RB0 + rr) * DIM + ec + 4 * c4;
    float a[8] = {0,0,0,0,0,0,0,0};
    gemv64<DIM, 8>(pthr, xs[0] + RB0, xs[1] + RB0, rr, a);

    float s; int b, col;
    if (tile_reduce(a, s, b, col))
        atomicAdd(&g_qkv[par][b][e0 + col], s);
}

// ---------------- K2: RoPE + attn(head=ks) + O GEMV. grid 256 = 16cg x 16ks
__global__ void __launch_bounds__(256) k_attn(const float* __restrict__ wo,
                                              const int* __restrict__ cpos,
                                              int par) {
    __shared__ float xo[2][HD];
    int t = threadIdx.x, lane = t & 31, wid = t >> 5;
    int cg = blockIdx.x & 15, ks = blockIdx.x >> 4;   // ks = head
    int rr = t >> 4, c4 = t & 15;

    // zero next-parity qkv accumulator (blocks 0..15, same-value redundancy-free)
    if (blockIdx.x < 16) {
        float* z = (float*)g_qkv[par ^ 1] + blockIdx.x * 384;
        for (int i = t; i < 384; i += 256) z[i] = 0.f;
    }

    if (wid < 2) {
        int b = wid;
        const float* q = &g_qkv[par][b][ks * HD];
        const float* k = &g_qkv[par][b][DIM + ks * HD];
        const float* v = &g_qkv[par][b][2 * DIM + ks * HD];
        int pos = cpos[0];
        float inv_freq = __expf(-(float)(2 * lane) * (1.f / HD) * logf(10000.f));
        float ang = (float)pos * inv_freq;
        float cs = cosf(ang), sn = sinf(ang);
        float q1 = q[lane], q2 = q[lane + 32];
        float k1 = k[lane], k2 = k[lane + 32];
        float q1r = q1 * cs - q2 * sn, q2r = q2 * cs + q1 * sn;
        float k1r = k1 * cs - k2 * sn, k2r = k2 * cs + k1 * sn;
        float dot = q1r * k1r + q2r * k2r;
#pragma unroll
        for (int o = 16; o; o >>= 1) dot += __shfl_xor_sync(0xffffffffu, dot, o);
        float sc = dot * 0.125f;
        float m = fmaxf(sc, 0.f);
        float es = __expf(sc - m);
        float w = es / (es + 2047.f * __expf(-m));
        xo[b][lane]      = w * v[lane];
        xo[b][lane + 32] = w * v[lane + 32];
    }
    __syncthreads();

    int e0 = cg * 64, RB0 = ks * 64;
    const float* pthr = wo + (size_t)(RB0 + rr) * DIM + e0 + 4 * c4;
    float a[8] = {0,0,0,0,0,0,0,0};
    gemv64<DIM, 4>(pthr, xo[0], xo[1], rr, a);

    float s; int b, col;
    if (tile_reduce(a, s, b, col))
        atomicAdd(&g_h[b][e0 + col], s);
}

// ---------------- K3: rms2 + gate|up GEMV. grid 352 = 88cg x 4ks ---------
__global__ void __launch_bounds__(256) k_gateup(const float* __restrict__ wg,
                                                const float* __restrict__ wu,
                                                const float* __restrict__ ln2,
                                                int par) {
    __shared__ float xs[2][DIM];
    rms_x(ln2, xs);

    int t = threadIdx.x, rr = t >> 4, c4 = t & 15;
    int cg = blockIdx.x % 88, ks = blockIdx.x / 88;
    int half = cg < 44 ? 0 : 1;
    int e0 = (cg - half * 44) * 64;
    int RB0 = ks * 256;
    const float* W = half ? wu : wg;

    const float* pthr = W + (size_t)(RB0 + rr) * FFN + e0 + 4 * c4;
    float a[8] = {0,0,0,0,0,0,0,0};
    gemv64<FFN, 16>(pthr, xs[0] + RB0, xs[1] + RB0, rr, a);

    float s; int b, col;
    if (tile_reduce(a, s, b, col))
        atomicAdd(&g_gp[par][half][b][e0 + col], s);
}

// ---------------- K4: silu + down GEMV. grid 176 = 16cg x 11ks -----------
__global__ void __launch_bounds__(256) k_down(const float* __restrict__ wd,
                                              int par) {
    __shared__ float xs[2][256];
    int t = threadIdx.x, rr = t >> 4, c4 = t & 15;
    int cg = blockIdx.x & 15, ks = blockIdx.x >> 4;
    int RB0 = ks * 256;

    // zero next-parity gate/up accumulator (blocks 0..10)
    if (blockIdx.x < 11) {
        float* z = (float*)g_gp[par ^ 1] + blockIdx.x * 1024;
        for (int i = t; i < 1024; i += 256) z[i] = 0.f;
    }

    for (int i = t; i < 512; i += 256) {
        int b = i >> 8, r = i & 255;
        float g = g_gp[par][0][b][RB0 + r];
        float u = g_gp[par][1][b][RB0 + r];
        xs[b][r] = g / (1.f + __expf(-g)) * u;
    }
    __syncthreads();

    int e0 = cg * 64;
    const float* pthr = wd + (size_t)(RB0 + rr) * DIM + e0 + 4 * c4;
    float a[8] = {0,0,0,0,0,0,0,0};
    gemv64<DIM, 16>(pthr, xs[0], xs[1], rr, a);

    float s; int b, col;
    if (tile_reduce(a, s, b, col))
        atomicAdd(&g_h[b][e0 + col], s);
}

// ---------------- K5: final rms -> out[0:2048], g_hn ----------------------
__global__ void __launch_bounds__(256) k_final(const float* __restrict__ normw,
                                               float* __restrict__ out) {
    __shared__ float xs[2][DIM];
    rms_x(normw, xs);
    int t = threadIdx.x;
    for (int i = t; i < DIM; i += 256) {
        g_hn[0][i] = xs[0][i];
        g_hn[1][i] = xs[1][i];
        out[i]       = xs[0][i];
        out[DIM + i] = xs[1][i];
    }
}

// ---------------- K6: lm_head GEMV. grid 500 ------------------------------
__global__ void __launch_bounds__(256) k_lmhead(const float* __restrict__ wlm,
                                                float* __restrict__ out) {
    __shared__ float xs[2][DIM];
    int t = threadIdx.x, rr = t >> 4, c4 = t & 15;
    for (int i = t; i < DIM; i += 256) {
        xs[0][i] = g_hn[0][i];
        xs[1][i] = g_hn[1][i];
    }
    __syncthreads();

    int e0 = blockIdx.x * 64;
    const float* pthr = wlm + (size_t)rr * VOCAB + e0 + 4 * c4;
    float a[8] = {0,0,0,0,0,0,0,0};
    gemv64<VOCAB, 64>(pthr, xs[0], xs[1], rr, a);

    float s; int b, col;
    if (tile_reduce(a, s, b, col))
        out[2 * DIM + (size_t)b * VOCAB + e0 + col] = s;
}

// ---------------- launcher ----------------
extern "C" void kernel_launch(void* const* d_in, const int* in_sizes, int n_in,
                              void* d_out, int out_size) {
    const float* emb  = (const float*)d_in[0];
    const int*   cpos = (const int*)d_in[2];
    const float* wq   = (const float*)d_in[4];
    const float* wk   = (const float*)d_in[5];
    const float* wv   = (const float*)d_in[6];
    const float* wo   = (const float*)d_in[7];
    const float* wg   = (const float*)d_in[8];
    const float* wu   = (const float*)d_in[9];
    const float* wd   = (const float*)d_in[10];
    const float* ln1  = (const float*)d_in[11];
    const float* ln2  = (const float*)d_in[12];
    const float* nw   = (const float*)d_in[13];
    const float* wlm  = (const float*)d_in[14];
    float* out = (float*)d_out;

    k_init<<<19, 1024>>>(emb);
    for (int l = 0; l < NL; l++) {
        int par = l & 1;
        size_t oqk = (size_t)l * DIM * DIM;
        size_t ogu = (size_t)l * DIM * FFN;
        k_qkv   <<<384, 256>>>(wq + oqk, wk + oqk, wv + oqk, ln1 + l * DIM, par);
        k_attn  <<<256, 256>>>(wo + oqk, cpos, par);
        k_gateup<<<352, 256>>>(wg + ogu, wu + ogu, ln2 + l * DIM, par);
        k_down  <<<176, 256>>>(wd + ogu, par);
    }
    k_final <<<1,   256>>>(nw, out);
    k_lmhead<<<500, 256>>>(wlm, out);
}

// round 8
// speedup vs baseline: 2.1115x; 1.0474x over previous
#include <cuda_runtime.h>
#include <cstdint>

#define NL   28
#define DIM  1024
#define NH   16
#define HD   64
#define FFN  2816
#define VOCAB 32000

// ---------------- device scratch ----------------
__device__ float g_h[2][DIM];              // residual stream (atomically updated)
__device__ float g_qkv[2][2][3 * DIM];     // [parity][batch][q|k|v]
__device__ float g_gp[2][2][2][FFN];       // [parity][gate/up][batch][col]
__device__ float g_hn[2][DIM];             // final normed hidden

// ---------------- helpers ----------------
__device__ __forceinline__ float block_sum(float v) {
    __shared__ float sh[8];
    int lane = threadIdx.x & 31, w = threadIdx.x >> 5;
#pragma unroll
    for (int o = 16; o; o >>= 1) v += __shfl_xor_sync(0xffffffffu, v, o);
    __syncthreads();
    if (lane == 0) sh[w] = v;
    __syncthreads();
    float r = sh[0];
#pragma unroll
    for (int i = 1; i < 8; i++) r += sh[i];
    return r;
}

#define FMA8(w4, x0, x1)                                                   \
    a[0] += (x0) * (w4).x; a[1] += (x0) * (w4).y;                          \
    a[2] += (x0) * (w4).z; a[3] += (x0) * (w4).w;                          \
    a[4] += (x1) * (w4).x; a[5] += (x1) * (w4).y;                          \
    a[6] += (x1) * (w4).z; a[7] += (x1) * (w4).w;

// 64-col tile GEMV: thread (rr = t>>4, c4 = t&15); pthr pre-offset to
// row (RB0+rr), col (e0 + 4*c4). xs pre-offset so local index = rr + p*16.
// Front-batches G=min(NPASS,16) float4 loads to maximize MLP.
template<int LD, int NPASS>
__device__ __forceinline__ void gemv64(const float* __restrict__ pthr,
                                       const float* __restrict__ xs0,
                                       const float* __restrict__ xs1,
                                       int rr, float* a) {
    constexpr int G = NPASS < 16 ? NPASS : 16;
#pragma unroll
    for (int g = 0; g < NPASS; g += G) {
        float4 w[G];
#pragma unroll
        for (int r = 0; r < G; r++)
            w[r] = *(const float4*)(pthr + (size_t)(g + r) * 16 * LD);
#pragma unroll
        for (int r = 0; r < G; r++) {
            int d = rr + (g + r) * 16;
            float x0 = xs0[d], x1 = xs1[d];
            FMA8(w[r], x0, x1);
        }
    }
}

// reduce a[8] over the 16 row-threads per col-quad. Returns true for t<128
// with s = sum, b = batch, col = column offset within the 64-col tile.
__device__ __forceinline__ bool tile_reduce(float* a, float& s, int& b, int& col) {
    __shared__ float red[8][16][8];
    int t = threadIdx.x, lane = t & 31, wid = t >> 5;
#pragma unroll
    for (int j = 0; j < 8; j++) a[j] += __shfl_xor_sync(0xffffffffu, a[j], 16);
    if (lane < 16)
#pragma unroll
        for (int j = 0; j < 8; j++) red[wid][lane][j] = a[j];
    __syncthreads();
    if (t >= 128) return false;
    int c4 = t >> 3, j = t & 7;
    float acc = 0.f;
#pragma unroll
    for (int w = 0; w < 8; w++) acc += red[w][c4][j];
    s = acc; b = j >> 2; col = c4 * 4 + (j & 3);
    return true;
}

// rms prologue: xs[b][i] = rms(g_h[b]) * gamma[i]
__device__ __forceinline__ void rms_x(const float* __restrict__ gamma,
                                      float (*xs)[DIM]) {
    int t = threadIdx.x;
    float s0 = 0.f, s1 = 0.f;
    for (int i = t; i < DIM; i += 256) {
        float v0 = g_h[0][i], v1 = g_h[1][i];
        xs[0][i] = v0; xs[1][i] = v1;
        s0 += v0 * v0; s1 += v1 * v1;
    }
    s0 = block_sum(s0);
    s1 = block_sum(s1);
    float r0 = rsqrtf(s0 * (1.f / DIM) + 1e-5f);
    float r1 = rsqrtf(s1 * (1.f / DIM) + 1e-5f);
    for (int i = t; i < DIM; i += 256) {
        float g = gamma[i];
        xs[0][i] *= r0 * g;
        xs[1][i] *= r1 * g;
    }
    __syncthreads();
}

// ---------------- init: residual <- emb, zero parity-0 accumulators ------
__global__ void k_init(const float* __restrict__ emb) {
    int i = blockIdx.x * blockDim.x + threadIdx.x;
    if (i < 2 * DIM) g_h[i / DIM][i % DIM] = emb[i];
    int z = i - 2 * DIM;
    if (z >= 0) {
        if (z < 2 * 3 * DIM)            ((float*)g_qkv[0])[z] = 0.f;
        else if (z < 2*3*DIM + 4*FFN)   ((float*)g_gp[0])[z - 2*3*DIM] = 0.f;
    }
}

// ---------------- K1: rms1 + QKV GEMV. grid 384 = 48cg x 8ks -------------
__global__ void __launch_bounds__(256, 2) k_qkv(const float* __restrict__ wq,
                                                const float* __restrict__ wk,
                                                const float* __restrict__ wv,
                                                const float* __restrict__ ln1,
                                                int par) {
    __shared__ float xs[2][DIM];
    rms_x(ln1, xs);

    int t = threadIdx.x, rr = t >> 4, c4 = t & 15;
    int cg = blockIdx.x % 48, ks = blockIdx.x / 48;
    int e0 = cg * 64, RB0 = ks * 128;
    const float* W; int ec;
    if (e0 < DIM)          { W = wq; ec = e0; }
    else if (e0 < 2 * DIM) { W = wk; ec = e0 - DIM; }
    else                   { W = wv; ec = e0 - 2 * DIM; }

    const float* pthr = W + (size_t)(RB0 + rr) * DIM + ec + 4 * c4;
    float a[8] = {0,0,0,0,0,0,0,0};
    gemv64<DIM, 8>(pthr, xs[0] + RB0, xs[1] + RB0, rr, a);

    float s; int b, col;
    if (tile_reduce(a, s, b, col))
        atomicAdd(&g_qkv[par][b][e0 + col], s);
}

// ---------------- K2: RoPE + attn(head=ks) + O GEMV. grid 256 = 16cg x 16ks
__global__ void __launch_bounds__(256, 2) k_attn(const float* __restrict__ wo,
                                                 const int* __restrict__ cpos,
                                                 int par) {
    __shared__ float xo[2][HD];
    int t = threadIdx.x, lane = t & 31, wid = t >> 5;
    int cg = blockIdx.x & 15, ks = blockIdx.x >> 4;   // ks = head
    int rr = t >> 4, c4 = t & 15;

    // zero next-parity qkv accumulator (blocks 0..15)
    if (blockIdx.x < 16) {
        float* z = (float*)g_qkv[par ^ 1] + blockIdx.x * 384;
        for (int i = t; i < 384; i += 256) z[i] = 0.f;
    }

    if (wid < 2) {
        int b = wid;
        const float* q = &g_qkv[par][b][ks * HD];
        const float* k = &g_qkv[par][b][DIM + ks * HD];
        const float* v = &g_qkv[par][b][2 * DIM + ks * HD];
        int pos = cpos[0];
        float inv_freq = __expf(-(float)(2 * lane) * (1.f / HD) * logf(10000.f));
        float ang = (float)pos * inv_freq;
        float cs = cosf(ang), sn = sinf(ang);
        float q1 = q[lane], q2 = q[lane + 32];
        float k1 = k[lane], k2 = k[lane + 32];
        float q1r = q1 * cs - q2 * sn, q2r = q2 * cs + q1 * sn;
        float k1r = k1 * cs - k2 * sn, k2r = k2 * cs + k1 * sn;
        float dot = q1r * k1r + q2r * k2r;
#pragma unroll
        for (int o = 16; o; o >>= 1) dot += __shfl_xor_sync(0xffffffffu, dot, o);
        float sc = dot * 0.125f;
        float m = fmaxf(sc, 0.f);
        float es = __expf(sc - m);
        float w = es / (es + 2047.f * __expf(-m));
        xo[b][lane]      = w * v[lane];
        xo[b][lane + 32] = w * v[lane + 32];
    }
    __syncthreads();

    int e0 = cg * 64, RB0 = ks * 64;
    const float* pthr = wo + (size_t)(RB0 + rr) * DIM + e0 + 4 * c4;
    float a[8] = {0,0,0,0,0,0,0,0};
    gemv64<DIM, 4>(pthr, xo[0], xo[1], rr, a);

    float s; int b, col;
    if (tile_reduce(a, s, b, col))
        atomicAdd(&g_h[b][e0 + col], s);
}

// ---------------- K3: rms2 + gate|up GEMV. grid 352 = 88cg x 4ks ---------
__global__ void __launch_bounds__(256, 2) k_gateup(const float* __restrict__ wg,
                                                   const float* __restrict__ wu,
                                                   const float* __restrict__ ln2,
                                                   int par) {
    __shared__ float xs[2][DIM];
    rms_x(ln2, xs);

    int t = threadIdx.x, rr = t >> 4, c4 = t & 15;
    int cg = blockIdx.x % 88, ks = blockIdx.x / 88;
    int half = cg < 44 ? 0 : 1;
    int e0 = (cg - half * 44) * 64;
    int RB0 = ks * 256;
    const float* W = half ? wu : wg;

    const float* pthr = W + (size_t)(RB0 + rr) * FFN + e0 + 4 * c4;
    float a[8] = {0,0,0,0,0,0,0,0};
    gemv64<FFN, 16>(pthr, xs[0] + RB0, xs[1] + RB0, rr, a);

    float s; int b, col;
    if (tile_reduce(a, s, b, col))
        atomicAdd(&g_gp[par][half][b][e0 + col], s);
}

// ---------------- K4: silu + down GEMV. grid 176 = 16cg x 11ks -----------
__global__ void __launch_bounds__(256, 2) k_down(const float* __restrict__ wd,
                                                 int par) {
    __shared__ float xs[2][256];
    int t = threadIdx.x, rr = t >> 4, c4 = t & 15;
    int cg = blockIdx.x & 15, ks = blockIdx.x >> 4;
    int RB0 = ks * 256;

    // zero next-parity gate/up accumulator (blocks 0..10)
    if (blockIdx.x < 11) {
        float* z = (float*)g_gp[par ^ 1] + blockIdx.x * 1024;
        for (int i = t; i < 1024; i += 256) z[i] = 0.f;
    }

    for (int i = t; i < 512; i += 256) {
        int b = i >> 8, r = i & 255;
        float g = g_gp[par][0][b][RB0 + r];
        float u = g_gp[par][1][b][RB0 + r];
        xs[b][r] = g / (1.f + __expf(-g)) * u;
    }
    __syncthreads();

    int e0 = cg * 64;
    const float* pthr = wd + (size_t)(RB0 + rr) * DIM + e0 + 4 * c4;
    float a[8] = {0,0,0,0,0,0,0,0};
    gemv64<DIM, 16>(pthr, xs[0], xs[1], rr, a);

    float s; int b, col;
    if (tile_reduce(a, s, b, col))
        atomicAdd(&g_h[b][e0 + col], s);
}

// ---------------- K5: final rms -> out[0:2048], g_hn ----------------------
__global__ void __launch_bounds__(256) k_final(const float* __restrict__ normw,
                                               float* __restrict__ out) {
    __shared__ float xs[2][DIM];
    rms_x(normw, xs);
    int t = threadIdx.x;
    for (int i = t; i < DIM; i += 256) {
        g_hn[0][i] = xs[0][i];
        g_hn[1][i] = xs[1][i];
        out[i]       = xs[0][i];
        out[DIM + i] = xs[1][i];
    }
}

// ---------------- K6: lm_head GEMV. grid 500 ------------------------------
__global__ void __launch_bounds__(256, 2) k_lmhead(const float* __restrict__ wlm,
                                                   float* __restrict__ out) {
    __shared__ float xs[2][DIM];
    int t = threadIdx.x, rr = t >> 4, c4 = t & 15;
    for (int i = t; i < DIM; i += 256) {
        xs[0][i] = g_hn[0][i];
        xs[1][i] = g_hn[1][i];
    }
    __syncthreads();

    int e0 = blockIdx.x * 64;
    const float* pthr = wlm + (size_t)rr * VOCAB + e0 + 4 * c4;
    float a[8] = {0,0,0,0,0,0,0,0};
    gemv64<VOCAB, 64>(pthr, xs[0], xs[1], rr, a);

    float s; int b, col;
    if (tile_reduce(a, s, b, col))
        out[2 * DIM + (size_t)b * VOCAB + e0 + col] = s;
}

// ---------------- launcher ----------------
extern "C" void kernel_launch(void* const* d_in, const int* in_sizes, int n_in,
                              void* d_out, int out_size) {
    const float* emb  = (const float*)d_in[0];
    const int*   cpos = (const int*)d_in[2];
    const float* wq   = (const float*)d_in[4];
    const float* wk   = (const float*)d_in[5];
    const float* wv   = (const float*)d_in[6];
    const float* wo   = (const float*)d_in[7];
    const float* wg   = (const float*)d_in[8];
    const float* wu   = (const float*)d_in[9];
    const float* wd   = (const float*)d_in[10];
    const float* ln1  = (const float*)d_in[11];
    const float* ln2  = (const float*)d_in[12];
    const float* nw   = (const float*)d_in[13];
    const float* wlm  = (const float*)d_in[14];
    float* out = (float*)d_out;

    k_init<<<19, 1024>>>(emb);
    for (int l = 0; l < NL; l++) {
        int par = l & 1;
        size_t oqk = (size_t)l * DIM * DIM;
        size_t ogu = (size_t)l * DIM * FFN;
        k_qkv   <<<384, 256>>>(wq + oqk, wk + oqk, wv + oqk, ln1 + l * DIM, par);
        k_attn  <<<256, 256>>>(wo + oqk, cpos, par);
        k_gateup<<<352, 256>>>(wg + ogu, wu + ogu, ln2 + l * DIM, par);
        k_down  <<<176, 256>>>(wd + ogu, par);
    }
    k_final <<<1,   256>>>(nw, out);
    k_lmhead<<<500, 256>>>(wlm, out);
}